// round 6
// baseline (speedup 1.0000x reference)
#include <cuda_runtime.h>
#include <cuda_fp16.h>
#include <cstdint>

// ============================================================================
// Conv2D per-sample dynamic filter via warp-level mma.sync (fp16 HMMA, f32 acc).
//   out[b,y,x,co] = sum_{dy,dx,ci} X[b,y+dy,x+dx,ci] * K[b,dy,dx,ci,co]
//
// R5->R6: register-pressure attack. No cross-stage A hold (LDG early in stage,
// STS late in same stage); B/A smem pointers recomputed per stage instead of
// persistent; explicit fragment arrays per (dx,j) so ptxas batches 8 LDS ahead
// of 16 back-to-back MMAs. Staging split across two MMA gaps.
// ============================================================================

#define THREADS 256

// filter, f16 fragment order: [b][dy][c16(4)][dx(3)][j(2)][pair(8)][lane(32)] x uint4
__device__ uint4 g_Kf4[16 * 3 * 4 * 3 * 2 * 8 * 32];

static __device__ __forceinline__ uint32_t smem_u32(const void* p) {
    uint32_t a;
    asm("{ .reg .u64 t; cvta.to.shared.u64 t, %1; cvt.u32.u64 %0, t; }"
        : "=r"(a) : "l"(p));
    return a;
}

static __device__ __forceinline__ uint32_t pack_h2(float lo, float hi) {
    __half2 h = __floats2half2_rn(lo, hi);
    return *reinterpret_cast<uint32_t*>(&h);
}

static __device__ __forceinline__ void cp16(uint32_t dst, const void* src) {
    asm volatile("cp.async.cg.shared.global [%0], [%1], 16;"
                 :: "r"(dst), "l"(src) : "memory");
}

#define CP_COMMIT() asm volatile("cp.async.commit_group;" ::: "memory")
#define CP_WAIT1()  asm volatile("cp.async.wait_group 1;" ::: "memory")

// D += A * B   (m16n8k16, f16 in, f32 acc)
#define MMA(d, a0, a1, a2, a3, b0, b1)                                        \
    asm volatile(                                                             \
        "mma.sync.aligned.m16n8k16.row.col.f32.f16.f16.f32 "                  \
        "{%0,%1,%2,%3}, {%4,%5,%6,%7}, {%8,%9}, {%0,%1,%2,%3};"               \
        : "+f"((d)[0]), "+f"((d)[1]), "+f"((d)[2]), "+f"((d)[3])              \
        : "r"(a0), "r"(a1), "r"(a2), "r"(a3), "r"(b0), "r"(b1))

// ---------------- pre-pass: filter -> f16 fragment order --------------------

__global__ void __launch_bounds__(256) kt_frag(const float* __restrict__ K) {
    int id = blockIdx.x * 256 + threadIdx.x;          // 0 .. 294911
    int lane = id & 31;
    int r = id >> 5;
    int p   = r & 7;  r >>= 3;
    int j   = r & 1;  r >>= 1;
    int dx  = r % 3;  r /= 3;
    int c16 = r & 3;  r >>= 2;
    int dy  = r % 3;
    int b   = r / 3;
    int g = lane >> 2, t = lane & 3;
    int k0  = c16 * 32 + j * 16 + 2 * t;
    int k1  = k0 + 8;
    int co0 = p * 16 + g;
    const float* src = K + ((size_t)(b * 9 + dy * 3 + dx) * 128) * 128;
    uint4 v;
    v.x = pack_h2(src[(size_t)k0 * 128 + co0], src[(size_t)(k0 + 1) * 128 + co0]);
    v.y = pack_h2(src[(size_t)k1 * 128 + co0], src[(size_t)(k1 + 1) * 128 + co0]);
    v.z = pack_h2(src[(size_t)k0 * 128 + co0 + 8], src[(size_t)(k0 + 1) * 128 + co0 + 8]);
    v.w = pack_h2(src[(size_t)k1 * 128 + co0 + 8], src[(size_t)(k1 + 1) * 128 + co0 + 8]);
    g_Kf4[id] = v;
}

// ---------------- main kernel ----------------------------------------------

// A tile: 130 px rows (128 real + 2 zero pad) x 32 f16, permuted k-word order.
// Row stride 24 words: g*24 mod 32 in {0,8,16,24} -> conflict-free.
static constexpr int A_STRIDE_W = 24;
static constexpr int A_BYTES    = 12544;                  // 130*96=12480, padded
static constexpr int B_BYTES    = 3 * 2 * 8 * 32 * 16;    // 24576
static constexpr int SMEM_B0    = 2 * A_BYTES;            // 25088
static constexpr int SMEM_TOTAL = SMEM_B0 + 3 * B_BYTES;  // 98816

__global__ void __launch_bounds__(THREADS, 2) conv_main(
    const float* __restrict__ X, float* __restrict__ out) {
    extern __shared__ char smem[];
    const uint32_t smem_base = smem_u32(smem);
    const int tid  = threadIdx.x;
    const int lane = tid & 31;
    const int wid  = tid >> 5;
    const int warp_m = wid & 3;           // 4 warps along M (32 rows each)
    const int warp_n = wid >> 2;          // 2 warps along N (64 cols each)
    const int g = lane >> 2, t = lane & 3;
    const int y = blockIdx.x;             // output row 0..125
    const int b = blockIdx.y;             // batch

    const float* Xbase = X + (((size_t)b * 128 + y) * 128) * 128;

    // zero the 2 pad rows (128,129) of both A buffers (feed only discarded acc)
    if (tid < 96) {
        int buf = tid / 48, w = tid % 48;
        reinterpret_cast<uint32_t*>(smem + buf * A_BYTES)[128 * A_STRIDE_W + w] = 0;
    }

    // A staging geometry: 1024 float4 per stage
    const int apx  = tid >> 3;            // base px (+32 per i)
    const int ach  = tid & 7;
    const int aj   = ach >> 2;
    const int ac   = ach & 3;
    const int ao0  = ((ac & 1) << 2) + (ac >> 1);
    const int awrd = apx * A_STRIDE_W + aj * 8 + ao0;

    auto a_ldg = [&](int s, uint32_t* ah) {
        const int dy = s >> 2, c16 = s & 3;
        const float* Arow = Xbase + (size_t)dy * 16384 + c16 * 32;
#pragma unroll
        for (int i = 0; i < 4; i++) {
            float4 v = *reinterpret_cast<const float4*>(
                Arow + (size_t)(apx + 32 * i) * 128 + ach * 4);
            ah[2 * i]     = pack_h2(v.x, v.y);
            ah[2 * i + 1] = pack_h2(v.z, v.w);
        }
    };
    auto a_sts = [&](int buf, const uint32_t* ah) {
        uint32_t* As = reinterpret_cast<uint32_t*>(smem + buf * A_BYTES);
#pragma unroll
        for (int i = 0; i < 4; i++) {
            As[awrd + i * 32 * A_STRIDE_W]     = ah[2 * i];
            As[awrd + i * 32 * A_STRIDE_W + 2] = ah[2 * i + 1];
        }
    };
    auto b_cp = [&](int s) {
        const int dy = s >> 2, c16 = s & 3;
        const uint4* Bsrc = g_Kf4 + ((size_t)((b * 3 + dy) * 4 + c16)) * 1536;
        const uint32_t bb = smem_base + SMEM_B0 + (s % 3) * B_BYTES;
#pragma unroll
        for (int i = 0; i < 6; i++) {
            int idx = tid + i * THREADS;
            cp16(bb + idx * 16, Bsrc + idx);
        }
    };

    float acc[2][8][4];
#pragma unroll
    for (int mt = 0; mt < 2; mt++)
#pragma unroll
        for (int nt = 0; nt < 8; nt++)
#pragma unroll
            for (int e = 0; e < 4; e++) acc[mt][nt][e] = 0.0f;

    // ---- prologue: stage 0 A, B0, B1 in flight ----
    {
        uint32_t ah[8];
        a_ldg(0, ah); a_sts(0, ah);
    }
    b_cp(0); CP_COMMIT();
    b_cp(1); CP_COMMIT();

    const int rbase = warp_m * 32 + g;
    const int a_off = rbase * A_STRIDE_W + 2 * t;     // word offset in A tile
    const int b_off = warp_n * 128 + lane;            // uint4 offset in B tile

#pragma unroll 1
    for (int s = 0; s < 12; s++) {
        CP_WAIT1();
        __syncthreads();

        // early A LDG for next stage (latency hidden under this stage's MMAs)
        uint32_t ah[8];
        if (s < 11) a_ldg(s + 1, ah);

        const uint32_t* Au = reinterpret_cast<const uint32_t*>(smem + (s & 1) * A_BYTES) + a_off;
        const uint4*    Bs = reinterpret_cast<const uint4*>(smem + SMEM_B0 + (s % 3) * B_BYTES) + b_off;

        auto do_dx = [&](int dx) {
#pragma unroll
            for (int j = 0; j < 2; j++) {
                const int ro = dx * A_STRIDE_W + j * 8;
                uint2 f[4];
                uint4 bv[4];
#pragma unroll
                for (int q = 0; q < 4; q++)
                    f[q] = *reinterpret_cast<const uint2*>(Au + ro + q * 8 * A_STRIDE_W);
#pragma unroll
                for (int p = 0; p < 4; p++)
                    bv[p] = Bs[((dx * 2 + j) * 8 + p) * 32];
#pragma unroll
                for (int p = 0; p < 4; p++) {
                    MMA(acc[0][2 * p],     f[0].x, f[1].x, f[0].y, f[1].y, bv[p].x, bv[p].y);
                    MMA(acc[0][2 * p + 1], f[0].x, f[1].x, f[0].y, f[1].y, bv[p].z, bv[p].w);
                    MMA(acc[1][2 * p],     f[2].x, f[3].x, f[2].y, f[3].y, bv[p].x, bv[p].y);
                    MMA(acc[1][2 * p + 1], f[2].x, f[3].x, f[2].y, f[3].y, bv[p].z, bv[p].w);
                }
            }
        };

        do_dx(0);
        if (s < 10) b_cp(s + 2);
        CP_COMMIT();
        do_dx(1);
        if (s < 11) a_sts((s + 1) & 1, ah);   // buffer (s+1)&1 not read this stage
        do_dx(2);
    }

    // ---- epilogue: direct STG (accumulator rows ARE output x) ----
    float* outp = out + (((size_t)b * 126 + y) * 126) * 128;
#pragma unroll
    for (int mt = 0; mt < 2; mt++) {
        const int x0 = warp_m * 32 + mt * 16 + g;        // always < 126
        const int x1 = x0 + 8;                           // may be 126/127
#pragma unroll
        for (int nt = 0; nt < 8; nt++) {
            const int co = warp_n * 64 + nt * 8 + 2 * t;
            float2 v0 = make_float2(acc[mt][nt][0], acc[mt][nt][1]);
            *reinterpret_cast<float2*>(outp + (size_t)x0 * 128 + co) = v0;
            if (x1 < 126) {
                float2 v1 = make_float2(acc[mt][nt][2], acc[mt][nt][3]);
                *reinterpret_cast<float2*>(outp + (size_t)x1 * 128 + co) = v1;
            }
        }
    }
}

// ---------------- launch ----------------------------------------------------

extern "C" void kernel_launch(void* const* d_in, const int* in_sizes, int n_in,
                              void* d_out, int out_size) {
    const float* X = (const float*)d_in[0];     // [16,128,128,128]
    const float* K = (const float*)d_in[1];     // [16,3,3,128,128]
    float* out = (float*)d_out;                 // [16,126,126,128]
    (void)in_sizes; (void)n_in; (void)out_size;

    cudaFuncSetAttribute(conv_main, cudaFuncAttributeMaxDynamicSharedMemorySize, SMEM_TOTAL);

    kt_frag<<<1152, 256>>>(K);
    conv_main<<<dim3(126, 16), THREADS, SMEM_TOTAL>>>(X, out);
}